// round 1
// baseline (speedup 1.0000x reference)
#include <cuda_runtime.h>

#define NN 100000
#define NE 1600000
#define D 48
#define NCONVS 6
#define NG 1000

typedef unsigned long long u64;

// Scratch state (no allocation allowed): node features + aggregation buffer.
__device__ float4 g_h[NN * 12];
__device__ float4 g_agg[NN * 12];

// ---------- packed f32x2 helpers ----------
__device__ __forceinline__ u64 fma2(u64 a, u64 b, u64 c) {
    u64 d;
    asm("fma.rn.f32x2 %0, %1, %2, %3;" : "=l"(d) : "l"(a), "l"(b), "l"(c));
    return d;
}
__device__ __forceinline__ u64 pack2(float lo, float hi) {
    u64 r;
    asm("mov.b64 %0, {%1, %2};" : "=l"(r) : "f"(lo), "f"(hi));
    return r;
}
__device__ __forceinline__ float2 unpack2(u64 v) {
    float2 f;
    asm("mov.b64 {%0, %1}, %2;" : "=f"(f.x), "=f"(f.y) : "l"(v));
    return f;
}

// acc[24] (f32x2 pairs) = b[0..47] ; then acc += x @ W  (W row-major [48,48] in smem)
__device__ __forceinline__ void gemm48(const float x[D], u64 acc[24],
                                       const float* __restrict__ ws,
                                       const float* __restrict__ bs) {
#pragma unroll
    for (int j = 0; j < 24; j++) acc[j] = *(const u64*)(bs + 2 * j);
#pragma unroll 4
    for (int k = 0; k < D; k++) {
        u64 xk = pack2(x[k], x[k]);
        const ulonglong2* wr = (const ulonglong2*)(ws + k * D);
#pragma unroll
        for (int jj = 0; jj < 12; jj++) {
            ulonglong2 w = wr[jj];
            acc[2 * jj]     = fma2(xk, w.x, acc[2 * jj]);
            acc[2 * jj + 1] = fma2(xk, w.y, acc[2 * jj + 1]);
        }
    }
}

// out = relu(x@W1 + b1) @ W2 + b2
__device__ __forceinline__ void mlp2_48(const float x[D], float out[D],
                                        const float* __restrict__ w1s, const float* __restrict__ b1s,
                                        const float* __restrict__ w2s, const float* __restrict__ b2s) {
    u64 acc[24];
    gemm48(x, acc, w1s, b1s);

    u64 acc2[24];
#pragma unroll
    for (int j = 0; j < 24; j++) acc2[j] = *(const u64*)(b2s + 2 * j);
#pragma unroll 2
    for (int kk = 0; kk < 24; kk++) {
        float2 hv = unpack2(acc[kk]);
        float h0 = fmaxf(hv.x, 0.f);
        float h1 = fmaxf(hv.y, 0.f);
        u64 hk0 = pack2(h0, h0);
        u64 hk1 = pack2(h1, h1);
        const ulonglong2* w0 = (const ulonglong2*)(w2s + (2 * kk) * D);
        const ulonglong2* w1r = (const ulonglong2*)(w2s + (2 * kk + 1) * D);
#pragma unroll
        for (int jj = 0; jj < 12; jj++) {
            ulonglong2 wa = w0[jj];
            acc2[2 * jj]     = fma2(hk0, wa.x, acc2[2 * jj]);
            acc2[2 * jj + 1] = fma2(hk0, wa.y, acc2[2 * jj + 1]);
        }
#pragma unroll
        for (int jj = 0; jj < 12; jj++) {
            ulonglong2 wb = w1r[jj];
            acc2[2 * jj]     = fma2(hk1, wb.x, acc2[2 * jj]);
            acc2[2 * jj + 1] = fma2(hk1, wb.y, acc2[2 * jj + 1]);
        }
    }
#pragma unroll
    for (int j = 0; j < 24; j++) {
        float2 o = unpack2(acc2[j]);
        out[2 * j] = o.x;
        out[2 * j + 1] = o.y;
    }
}

// ---------- kernels ----------

__global__ void embed_kernel(const int* __restrict__ an, const float4* __restrict__ emb4) {
    int i = blockIdx.x * blockDim.x + threadIdx.x;  // over NN*12
    if (i >= NN * 12) return;
    int node = i / 12;
    int v = i - node * 12;
    g_h[i] = emb4[an[node] * 12 + v];
    g_agg[i] = make_float4(0.f, 0.f, 0.f, 0.f);
}

// shared layout: [0:2304) w1, [2304:4608) w2, [4608:4656) b1, [4656:4704) b2
__device__ __forceinline__ void load_weights_smem(float* s,
                                                  const float* __restrict__ w1, const float* __restrict__ b1,
                                                  const float* __restrict__ w2, const float* __restrict__ b2,
                                                  int layer) {
    const float* lw1 = w1 + layer * D * D;
    const float* lw2 = w2 + layer * D * D;
    for (int i = threadIdx.x; i < D * D; i += blockDim.x) {
        s[i] = lw1[i];
        s[2304 + i] = lw2[i];
    }
    if (threadIdx.x < D) {
        s[4608 + threadIdx.x] = b1[layer * D + threadIdx.x];
        s[4656 + threadIdx.x] = b2[layer * D + threadIdx.x];
    }
    __syncthreads();
}

__global__ __launch_bounds__(256, 1) void edge_kernel(
    const int* __restrict__ edge,
    const float* __restrict__ w1, const float* __restrict__ b1,
    const float* __restrict__ w2, const float* __restrict__ b2, int layer) {
    __shared__ __align__(16) float s[4704];
    load_weights_smem(s, w1, b1, w2, b2, layer);

    int e = blockIdx.x * 256 + threadIdx.x;
    if (e >= NE) return;
    int srcn = edge[e];
    int dstn = edge[NE + e];

    const float4* hs = &g_h[srcn * 12];
    const float4* hd = &g_h[dstn * 12];
    float x[D];
#pragma unroll
    for (int v = 0; v < 12; v++) {
        float4 a = hs[v];
        float4 b = hd[v];
        x[4 * v + 0] = a.x * b.x;
        x[4 * v + 1] = a.y * b.y;
        x[4 * v + 2] = a.z * b.z;
        x[4 * v + 3] = a.w * b.w;
    }

    float m[D];
    mlp2_48(x, m, s, s + 4608, s + 2304, s + 4656);

    float* aggp = (float*)&g_agg[dstn * 12];
#pragma unroll
    for (int v = 0; v < 12; v++) {
        asm volatile("red.global.add.v4.f32 [%0], {%1, %2, %3, %4};"
                     :: "l"(aggp + 4 * v),
                        "f"(m[4 * v]), "f"(m[4 * v + 1]), "f"(m[4 * v + 2]), "f"(m[4 * v + 3])
                     : "memory");
    }
}

__global__ __launch_bounds__(256, 1) void update_kernel(
    const float* __restrict__ w1, const float* __restrict__ b1,
    const float* __restrict__ w2, const float* __restrict__ b2, int layer) {
    __shared__ __align__(16) float s[4704];
    load_weights_smem(s, w1, b1, w2, b2, layer);

    int n = blockIdx.x * 256 + threadIdx.x;
    if (n >= NN) return;

    float4* aggp = &g_agg[n * 12];
    float x[D];
    const float4 z = make_float4(0.f, 0.f, 0.f, 0.f);
#pragma unroll
    for (int v = 0; v < 12; v++) {
        float4 a = aggp[v];
        x[4 * v + 0] = a.x;
        x[4 * v + 1] = a.y;
        x[4 * v + 2] = a.z;
        x[4 * v + 3] = a.w;
        aggp[v] = z;  // reset for next layer's scatter
    }

    float u[D];
    mlp2_48(x, u, s, s + 4608, s + 2304, s + 4656);

    float4* hp = &g_h[n * 12];
#pragma unroll
    for (int v = 0; v < 12; v++) {
        float4 h = hp[v];
        h.x += u[4 * v + 0];
        h.y += u[4 * v + 1];
        h.z += u[4 * v + 2];
        h.w += u[4 * v + 3];
        hp[v] = h;
    }
}

__global__ __launch_bounds__(256, 1) void readout_kernel(
    const int* __restrict__ gid,
    const float* __restrict__ rw1, const float* __restrict__ rb1,
    const float* __restrict__ rw2, const float* __restrict__ rb2,
    float* __restrict__ out) {
    // shared: [0:2304) w1, [2304:2352) b1, [2352:2400) w2 (48x1), [2400] b2
    __shared__ __align__(16) float s[2402];
    for (int i = threadIdx.x; i < D * D; i += blockDim.x) s[i] = rw1[i];
    if (threadIdx.x < D) {
        s[2304 + threadIdx.x] = rb1[threadIdx.x];
        s[2352 + threadIdx.x] = rw2[threadIdx.x];
    }
    if (threadIdx.x == 0) s[2400] = rb2[0];
    __syncthreads();

    int n = blockIdx.x * 256 + threadIdx.x;
    if (n >= NN) return;

    const float4* hp = &g_h[n * 12];
    float x[D];
#pragma unroll
    for (int v = 0; v < 12; v++) {
        float4 a = hp[v];
        x[4 * v + 0] = a.x;
        x[4 * v + 1] = a.y;
        x[4 * v + 2] = a.z;
        x[4 * v + 3] = a.w;
    }

    u64 acc[24];
    gemm48(x, acc, s, s + 2304);

    float y = s[2400];
#pragma unroll
    for (int kk = 0; kk < 24; kk++) {
        float2 hv = unpack2(acc[kk]);
        y += fmaxf(hv.x, 0.f) * s[2352 + 2 * kk];
        y += fmaxf(hv.y, 0.f) * s[2352 + 2 * kk + 1];
    }

    atomicAdd(&out[gid[n]], y);
}

extern "C" void kernel_launch(void* const* d_in, const int* in_sizes, int n_in,
                              void* d_out, int out_size) {
    const int*   an   = (const int*)d_in[0];
    const int*   edge = (const int*)d_in[1];
    const int*   gid  = (const int*)d_in[2];
    const float* emb  = (const float*)d_in[3];
    const float* mw1  = (const float*)d_in[4];
    const float* mb1  = (const float*)d_in[5];
    const float* mw2  = (const float*)d_in[6];
    const float* mb2  = (const float*)d_in[7];
    const float* uw1  = (const float*)d_in[8];
    const float* ub1  = (const float*)d_in[9];
    const float* uw2  = (const float*)d_in[10];
    const float* ub2  = (const float*)d_in[11];
    const float* rw1  = (const float*)d_in[12];
    const float* rb1  = (const float*)d_in[13];
    const float* rw2  = (const float*)d_in[14];
    const float* rb2  = (const float*)d_in[15];
    float* out = (float*)d_out;

    embed_kernel<<<(NN * 12 + 255) / 256, 256>>>(an, (const float4*)emb);

    for (int l = 0; l < NCONVS; l++) {
        edge_kernel<<<(NE + 255) / 256, 256>>>(edge, mw1, mb1, mw2, mb2, l);
        update_kernel<<<(NN + 255) / 256, 256>>>(uw1, ub1, uw2, ub2, l);
    }

    cudaMemsetAsync(out, 0, NG * sizeof(float));
    readout_kernel<<<(NN + 255) / 256, 256>>>(gid, rw1, rb1, rw2, rb2, out);
}

// round 2
// speedup vs baseline: 1.0014x; 1.0014x over previous
#include <cuda_runtime.h>

#define NN 100000
#define NE 1600000
#define D 48
#define NCONVS 6
#define NG 1000

typedef unsigned long long u64;

// Scratch state (no allocation allowed): node features + aggregation buffer.
__device__ float4 g_h[NN * 12];
__device__ float4 g_agg[NN * 12];

// ---------- packed f32x2 helpers ----------
__device__ __forceinline__ u64 fma2(u64 a, u64 b, u64 c) {
    u64 d;
    asm("fma.rn.f32x2 %0, %1, %2, %3;" : "=l"(d) : "l"(a), "l"(b), "l"(c));
    return d;
}
__device__ __forceinline__ u64 pack2(float lo, float hi) {
    u64 r;
    asm("mov.b64 %0, {%1, %2};" : "=l"(r) : "f"(lo), "f"(hi));
    return r;
}
__device__ __forceinline__ float2 unpack2(u64 v) {
    float2 f;
    asm("mov.b64 {%0, %1}, %2;" : "=f"(f.x), "=f"(f.y) : "l"(v));
    return f;
}

// acc[24] (f32x2 pairs) = b[0..47] ; then acc += x @ W  (W row-major [48,48] in smem)
__device__ __forceinline__ void gemm48(const float x[D], u64 acc[24],
                                       const float* __restrict__ ws,
                                       const float* __restrict__ bs) {
#pragma unroll
    for (int j = 0; j < 24; j++) acc[j] = *(const u64*)(bs + 2 * j);
#pragma unroll 4
    for (int k = 0; k < D; k++) {
        u64 xk = pack2(x[k], x[k]);
        const ulonglong2* wr = (const ulonglong2*)(ws + k * D);
#pragma unroll
        for (int jj = 0; jj < 12; jj++) {
            ulonglong2 w = wr[jj];
            acc[2 * jj]     = fma2(xk, w.x, acc[2 * jj]);
            acc[2 * jj + 1] = fma2(xk, w.y, acc[2 * jj + 1]);
        }
    }
}

// out = relu(x@W1 + b1) @ W2 + b2
__device__ __forceinline__ void mlp2_48(const float x[D], float out[D],
                                        const float* __restrict__ w1s, const float* __restrict__ b1s,
                                        const float* __restrict__ w2s, const float* __restrict__ b2s) {
    u64 acc[24];
    gemm48(x, acc, w1s, b1s);

    u64 acc2[24];
#pragma unroll
    for (int j = 0; j < 24; j++) acc2[j] = *(const u64*)(b2s + 2 * j);
#pragma unroll 2
    for (int kk = 0; kk < 24; kk++) {
        float2 hv = unpack2(acc[kk]);
        float h0 = fmaxf(hv.x, 0.f);
        float h1 = fmaxf(hv.y, 0.f);
        u64 hk0 = pack2(h0, h0);
        u64 hk1 = pack2(h1, h1);
        const ulonglong2* w0 = (const ulonglong2*)(w2s + (2 * kk) * D);
        const ulonglong2* w1r = (const ulonglong2*)(w2s + (2 * kk + 1) * D);
#pragma unroll
        for (int jj = 0; jj < 12; jj++) {
            ulonglong2 wa = w0[jj];
            acc2[2 * jj]     = fma2(hk0, wa.x, acc2[2 * jj]);
            acc2[2 * jj + 1] = fma2(hk0, wa.y, acc2[2 * jj + 1]);
        }
#pragma unroll
        for (int jj = 0; jj < 12; jj++) {
            ulonglong2 wb = w1r[jj];
            acc2[2 * jj]     = fma2(hk1, wb.x, acc2[2 * jj]);
            acc2[2 * jj + 1] = fma2(hk1, wb.y, acc2[2 * jj + 1]);
        }
    }
#pragma unroll
    for (int j = 0; j < 24; j++) {
        float2 o = unpack2(acc2[j]);
        out[2 * j] = o.x;
        out[2 * j + 1] = o.y;
    }
}

// ---------- kernels ----------

__global__ void embed_kernel(const int* __restrict__ an, const float4* __restrict__ emb4) {
    int i = blockIdx.x * blockDim.x + threadIdx.x;  // over NN*12
    if (i >= NN * 12) return;
    int node = i / 12;
    int v = i - node * 12;
    g_h[i] = emb4[an[node] * 12 + v];
    g_agg[i] = make_float4(0.f, 0.f, 0.f, 0.f);
}

// shared layout: [0:2304) w1, [2304:4608) w2, [4608:4656) b1, [4656:4704) b2
__device__ __forceinline__ void load_weights_smem(float* s,
                                                  const float* __restrict__ w1, const float* __restrict__ b1,
                                                  const float* __restrict__ w2, const float* __restrict__ b2,
                                                  int layer) {
    const float* lw1 = w1 + layer * D * D;
    const float* lw2 = w2 + layer * D * D;
    for (int i = threadIdx.x; i < D * D; i += blockDim.x) {
        s[i] = lw1[i];
        s[2304 + i] = lw2[i];
    }
    if (threadIdx.x < D) {
        s[4608 + threadIdx.x] = b1[layer * D + threadIdx.x];
        s[4656 + threadIdx.x] = b2[layer * D + threadIdx.x];
    }
    __syncthreads();
}

__global__ __launch_bounds__(256, 1) void edge_kernel(
    const int* __restrict__ edge,
    const float* __restrict__ w1, const float* __restrict__ b1,
    const float* __restrict__ w2, const float* __restrict__ b2, int layer) {
    __shared__ __align__(16) float s[4704];
    load_weights_smem(s, w1, b1, w2, b2, layer);

    int e = blockIdx.x * 256 + threadIdx.x;
    if (e >= NE) return;
    int srcn = edge[e];
    int dstn = edge[NE + e];

    const float4* hs = &g_h[srcn * 12];
    const float4* hd = &g_h[dstn * 12];
    float x[D];
#pragma unroll
    for (int v = 0; v < 12; v++) {
        float4 a = hs[v];
        float4 b = hd[v];
        x[4 * v + 0] = a.x * b.x;
        x[4 * v + 1] = a.y * b.y;
        x[4 * v + 2] = a.z * b.z;
        x[4 * v + 3] = a.w * b.w;
    }

    float m[D];
    mlp2_48(x, m, s, s + 4608, s + 2304, s + 4656);

    float* aggp = (float*)&g_agg[dstn * 12];
#pragma unroll
    for (int v = 0; v < 12; v++) {
        asm volatile("red.global.add.v4.f32 [%0], {%1, %2, %3, %4};"
                     :: "l"(aggp + 4 * v),
                        "f"(m[4 * v]), "f"(m[4 * v + 1]), "f"(m[4 * v + 2]), "f"(m[4 * v + 3])
                     : "memory");
    }
}

__global__ __launch_bounds__(256, 1) void update_kernel(
    const float* __restrict__ w1, const float* __restrict__ b1,
    const float* __restrict__ w2, const float* __restrict__ b2, int layer) {
    __shared__ __align__(16) float s[4704];
    load_weights_smem(s, w1, b1, w2, b2, layer);

    int n = blockIdx.x * 256 + threadIdx.x;
    if (n >= NN) return;

    float4* aggp = &g_agg[n * 12];
    float x[D];
    const float4 z = make_float4(0.f, 0.f, 0.f, 0.f);
#pragma unroll
    for (int v = 0; v < 12; v++) {
        float4 a = aggp[v];
        x[4 * v + 0] = a.x;
        x[4 * v + 1] = a.y;
        x[4 * v + 2] = a.z;
        x[4 * v + 3] = a.w;
        aggp[v] = z;  // reset for next layer's scatter
    }

    float u[D];
    mlp2_48(x, u, s, s + 4608, s + 2304, s + 4656);

    float4* hp = &g_h[n * 12];
#pragma unroll
    for (int v = 0; v < 12; v++) {
        float4 h = hp[v];
        h.x += u[4 * v + 0];
        h.y += u[4 * v + 1];
        h.z += u[4 * v + 2];
        h.w += u[4 * v + 3];
        hp[v] = h;
    }
}

__global__ __launch_bounds__(256, 1) void readout_kernel(
    const int* __restrict__ gid,
    const float* __restrict__ rw1, const float* __restrict__ rb1,
    const float* __restrict__ rw2, const float* __restrict__ rb2,
    float* __restrict__ out) {
    // shared: [0:2304) w1, [2304:2352) b1, [2352:2400) w2 (48x1), [2400] b2
    __shared__ __align__(16) float s[2402];
    for (int i = threadIdx.x; i < D * D; i += blockDim.x) s[i] = rw1[i];
    if (threadIdx.x < D) {
        s[2304 + threadIdx.x] = rb1[threadIdx.x];
        s[2352 + threadIdx.x] = rw2[threadIdx.x];
    }
    if (threadIdx.x == 0) s[2400] = rb2[0];
    __syncthreads();

    int n = blockIdx.x * 256 + threadIdx.x;
    if (n >= NN) return;

    const float4* hp = &g_h[n * 12];
    float x[D];
#pragma unroll
    for (int v = 0; v < 12; v++) {
        float4 a = hp[v];
        x[4 * v + 0] = a.x;
        x[4 * v + 1] = a.y;
        x[4 * v + 2] = a.z;
        x[4 * v + 3] = a.w;
    }

    u64 acc[24];
    gemm48(x, acc, s, s + 2304);

    float y = s[2400];
#pragma unroll
    for (int kk = 0; kk < 24; kk++) {
        float2 hv = unpack2(acc[kk]);
        y += fmaxf(hv.x, 0.f) * s[2352 + 2 * kk];
        y += fmaxf(hv.y, 0.f) * s[2352 + 2 * kk + 1];
    }

    atomicAdd(&out[gid[n]], y);
}

extern "C" void kernel_launch(void* const* d_in, const int* in_sizes, int n_in,
                              void* d_out, int out_size) {
    const int*   an   = (const int*)d_in[0];
    const int*   edge = (const int*)d_in[1];
    const int*   gid  = (const int*)d_in[2];
    const float* emb  = (const float*)d_in[3];
    const float* mw1  = (const float*)d_in[4];
    const float* mb1  = (const float*)d_in[5];
    const float* mw2  = (const float*)d_in[6];
    const float* mb2  = (const float*)d_in[7];
    const float* uw1  = (const float*)d_in[8];
    const float* ub1  = (const float*)d_in[9];
    const float* uw2  = (const float*)d_in[10];
    const float* ub2  = (const float*)d_in[11];
    const float* rw1  = (const float*)d_in[12];
    const float* rb1  = (const float*)d_in[13];
    const float* rw2  = (const float*)d_in[14];
    const float* rb2  = (const float*)d_in[15];
    float* out = (float*)d_out;

    embed_kernel<<<(NN * 12 + 255) / 256, 256>>>(an, (const float4*)emb);

    for (int l = 0; l < NCONVS; l++) {
        edge_kernel<<<(NE + 255) / 256, 256>>>(edge, mw1, mb1, mw2, mb2, l);
        update_kernel<<<(NN + 255) / 256, 256>>>(uw1, ub1, uw2, ub2, l);
    }

    cudaMemsetAsync(out, 0, NG * sizeof(float));
    readout_kernel<<<(NN + 255) / 256, 256>>>(gid, rw1, rb1, rw2, rb2, out);
}

// round 3
// speedup vs baseline: 1.0152x; 1.0138x over previous
#include <cuda_runtime.h>

#define NN 100000
#define NE 1600000
#define D 48
#define NCONVS 6
#define NG 1000

typedef unsigned long long u64;

// Scratch state (no allocation allowed): node features + aggregation buffer.
__device__ float4 g_h[NN * 12];
__device__ float4 g_agg[NN * 12];

// ---------- packed f32x2 helpers ----------
__device__ __forceinline__ u64 fma2(u64 a, u64 b, u64 c) {
    u64 d;
    asm("fma.rn.f32x2 %0, %1, %2, %3;" : "=l"(d) : "l"(a), "l"(b), "l"(c));
    return d;
}
__device__ __forceinline__ u64 pack2(float lo, float hi) {
    u64 r;
    asm("mov.b64 %0, {%1, %2};" : "=l"(r) : "f"(lo), "f"(hi));
    return r;
}
__device__ __forceinline__ float2 unpack2(u64 v) {
    float2 f;
    asm("mov.b64 {%0, %1}, %2;" : "=f"(f.x), "=f"(f.y) : "l"(v));
    return f;
}

// Half-width GEMM: acc[12] (24 outputs) = bs[0..23] + x @ ws[:, half*24 : half*24+24]
// ws points at (W + half*24), row stride D floats.
__device__ __forceinline__ void gemm48_half(const float x[D], u64 acc[12],
                                            const float* __restrict__ ws,
                                            const float* __restrict__ bs) {
#pragma unroll
    for (int j = 0; j < 12; j++) acc[j] = *(const u64*)(bs + 2 * j);
#pragma unroll 4
    for (int k = 0; k < D; k++) {
        u64 xk = pack2(x[k], x[k]);
        const ulonglong2* wr = (const ulonglong2*)(ws + k * D);
#pragma unroll
        for (int jj = 0; jj < 6; jj++) {
            ulonglong2 w = wr[jj];
            acc[2 * jj]     = fma2(xk, w.x, acc[2 * jj]);
            acc[2 * jj + 1] = fma2(xk, w.y, acc[2 * jj + 1]);
        }
    }
}

// out = relu(x@W1 + b1) @ W2 + b2, computed in 24-wide output halves to keep
// live accumulator registers at 12 u64 (fits 2 CTAs/SM under 128 regs).
__device__ __forceinline__ void mlp2_48(const float x[D], float out[D],
                                        const float* __restrict__ w1s, const float* __restrict__ b1s,
                                        const float* __restrict__ w2s, const float* __restrict__ b2s) {
    float hid[D];
#pragma unroll 1
    for (int half = 0; half < 2; half++) {
        u64 acc[12];
        gemm48_half(x, acc, w1s + half * 24, b1s + half * 24);
#pragma unroll
        for (int j = 0; j < 12; j++) {
            float2 v = unpack2(acc[j]);
            hid[half * 24 + 2 * j]     = fmaxf(v.x, 0.f);
            hid[half * 24 + 2 * j + 1] = fmaxf(v.y, 0.f);
        }
    }
#pragma unroll 1
    for (int half = 0; half < 2; half++) {
        u64 acc[12];
        gemm48_half(hid, acc, w2s + half * 24, b2s + half * 24);
#pragma unroll
        for (int j = 0; j < 12; j++) {
            float2 v = unpack2(acc[j]);
            out[half * 24 + 2 * j]     = v.x;
            out[half * 24 + 2 * j + 1] = v.y;
        }
    }
}

// ---------- kernels ----------

__global__ void embed_kernel(const int* __restrict__ an, const float4* __restrict__ emb4) {
    int i = blockIdx.x * blockDim.x + threadIdx.x;  // over NN*12
    if (i >= NN * 12) return;
    int node = i / 12;
    int v = i - node * 12;
    g_h[i] = emb4[an[node] * 12 + v];
    g_agg[i] = make_float4(0.f, 0.f, 0.f, 0.f);
}

// shared layout: [0:2304) w1, [2304:4608) w2, [4608:4656) b1, [4656:4704) b2
__device__ __forceinline__ void load_weights_smem(float* s,
                                                  const float* __restrict__ w1, const float* __restrict__ b1,
                                                  const float* __restrict__ w2, const float* __restrict__ b2,
                                                  int layer) {
    const float* lw1 = w1 + layer * D * D;
    const float* lw2 = w2 + layer * D * D;
    for (int i = threadIdx.x; i < D * D; i += blockDim.x) {
        s[i] = lw1[i];
        s[2304 + i] = lw2[i];
    }
    if (threadIdx.x < D) {
        s[4608 + threadIdx.x] = b1[layer * D + threadIdx.x];
        s[4656 + threadIdx.x] = b2[layer * D + threadIdx.x];
    }
    __syncthreads();
}

__global__ __launch_bounds__(256, 2) void edge_kernel(
    const int* __restrict__ edge,
    const float* __restrict__ w1, const float* __restrict__ b1,
    const float* __restrict__ w2, const float* __restrict__ b2, int layer) {
    __shared__ __align__(16) float s[4704];
    load_weights_smem(s, w1, b1, w2, b2, layer);

    int e = blockIdx.x * 256 + threadIdx.x;  // NE divisible by 256, no guard needed
    int srcn = edge[e];
    int dstn = edge[NE + e];

    const float4* hs = &g_h[srcn * 12];
    const float4* hd = &g_h[dstn * 12];
    float x[D];
#pragma unroll
    for (int v = 0; v < 12; v++) {
        float4 a = hs[v];
        float4 b = hd[v];
        x[4 * v + 0] = a.x * b.x;
        x[4 * v + 1] = a.y * b.y;
        x[4 * v + 2] = a.z * b.z;
        x[4 * v + 3] = a.w * b.w;
    }

    float m[D];
    mlp2_48(x, m, s, s + 4608, s + 2304, s + 4656);

    float* aggp = (float*)&g_agg[dstn * 12];
#pragma unroll
    for (int v = 0; v < 12; v++) {
        asm volatile("red.global.add.v4.f32 [%0], {%1, %2, %3, %4};"
                     :: "l"(aggp + 4 * v),
                        "f"(m[4 * v]), "f"(m[4 * v + 1]), "f"(m[4 * v + 2]), "f"(m[4 * v + 3])
                     : "memory");
    }
}

__global__ __launch_bounds__(256, 2) void update_kernel(
    const float* __restrict__ w1, const float* __restrict__ b1,
    const float* __restrict__ w2, const float* __restrict__ b2, int layer) {
    __shared__ __align__(16) float s[4704];
    load_weights_smem(s, w1, b1, w2, b2, layer);

    int n = blockIdx.x * 256 + threadIdx.x;
    if (n >= NN) return;

    float4* aggp = &g_agg[n * 12];
    float x[D];
    const float4 z = make_float4(0.f, 0.f, 0.f, 0.f);
#pragma unroll
    for (int v = 0; v < 12; v++) {
        float4 a = aggp[v];
        x[4 * v + 0] = a.x;
        x[4 * v + 1] = a.y;
        x[4 * v + 2] = a.z;
        x[4 * v + 3] = a.w;
        aggp[v] = z;  // reset for next layer's scatter
    }

    float u[D];
    mlp2_48(x, u, s, s + 4608, s + 2304, s + 4656);

    float4* hp = &g_h[n * 12];
#pragma unroll
    for (int v = 0; v < 12; v++) {
        float4 h = hp[v];
        h.x += u[4 * v + 0];
        h.y += u[4 * v + 1];
        h.z += u[4 * v + 2];
        h.w += u[4 * v + 3];
        hp[v] = h;
    }
}

__global__ __launch_bounds__(256, 2) void readout_kernel(
    const int* __restrict__ gid,
    const float* __restrict__ rw1, const float* __restrict__ rb1,
    const float* __restrict__ rw2, const float* __restrict__ rb2,
    float* __restrict__ out) {
    // shared: [0:2304) w1, [2304:2352) b1, [2352:2400) w2 (48x1), [2400] b2
    __shared__ __align__(16) float s[2402];
    for (int i = threadIdx.x; i < D * D; i += blockDim.x) s[i] = rw1[i];
    if (threadIdx.x < D) {
        s[2304 + threadIdx.x] = rb1[threadIdx.x];
        s[2352 + threadIdx.x] = rw2[threadIdx.x];
    }
    if (threadIdx.x == 0) s[2400] = rb2[0];
    __syncthreads();

    int n = blockIdx.x * 256 + threadIdx.x;
    if (n >= NN) return;

    const float4* hp = &g_h[n * 12];
    float x[D];
#pragma unroll
    for (int v = 0; v < 12; v++) {
        float4 a = hp[v];
        x[4 * v + 0] = a.x;
        x[4 * v + 1] = a.y;
        x[4 * v + 2] = a.z;
        x[4 * v + 3] = a.w;
    }

    float y = s[2400];
#pragma unroll 1
    for (int half = 0; half < 2; half++) {
        u64 acc[12];
        gemm48_half(x, acc, s + half * 24, s + 2304 + half * 24);
#pragma unroll
        for (int j = 0; j < 12; j++) {
            float2 v = unpack2(acc[j]);
            y += fmaxf(v.x, 0.f) * s[2352 + half * 24 + 2 * j];
            y += fmaxf(v.y, 0.f) * s[2352 + half * 24 + 2 * j + 1];
        }
    }

    atomicAdd(&out[gid[n]], y);
}

extern "C" void kernel_launch(void* const* d_in, const int* in_sizes, int n_in,
                              void* d_out, int out_size) {
    const int*   an   = (const int*)d_in[0];
    const int*   edge = (const int*)d_in[1];
    const int*   gid  = (const int*)d_in[2];
    const float* emb  = (const float*)d_in[3];
    const float* mw1  = (const float*)d_in[4];
    const float* mb1  = (const float*)d_in[5];
    const float* mw2  = (const float*)d_in[6];
    const float* mb2  = (const float*)d_in[7];
    const float* uw1  = (const float*)d_in[8];
    const float* ub1  = (const float*)d_in[9];
    const float* uw2  = (const float*)d_in[10];
    const float* ub2  = (const float*)d_in[11];
    const float* rw1  = (const float*)d_in[12];
    const float* rb1  = (const float*)d_in[13];
    const float* rw2  = (const float*)d_in[14];
    const float* rb2  = (const float*)d_in[15];
    float* out = (float*)d_out;

    embed_kernel<<<(NN * 12 + 255) / 256, 256>>>(an, (const float4*)emb);

    for (int l = 0; l < NCONVS; l++) {
        edge_kernel<<<NE / 256, 256>>>(edge, mw1, mb1, mw2, mb2, l);
        update_kernel<<<(NN + 255) / 256, 256>>>(uw1, ub1, uw2, ub2, l);
    }

    cudaMemsetAsync(out, 0, NG * sizeof(float));
    readout_kernel<<<(NN + 255) / 256, 256>>>(gid, rw1, rb1, rw2, rb2, out);
}

// round 4
// speedup vs baseline: 1.1399x; 1.1228x over previous
#include <cuda_runtime.h>

#define NN 100000
#define NE 1600000
#define D 48
#define NCONVS 6
#define NG 1000

typedef unsigned long long u64;

// Scratch state (no allocation allowed): node features + aggregation buffer.
__device__ float4 g_h[NN * 12];
__device__ float4 g_agg[NN * 12];

// ---------- packed f32x2 helpers ----------
__device__ __forceinline__ u64 fma2(u64 a, u64 b, u64 c) {
    u64 d;
    asm("fma.rn.f32x2 %0, %1, %2, %3;" : "=l"(d) : "l"(a), "l"(b), "l"(c));
    return d;
}
__device__ __forceinline__ u64 pack2(float lo, float hi) {
    u64 r;
    asm("mov.b64 %0, {%1, %2};" : "=l"(r) : "f"(lo), "f"(hi));
    return r;
}
__device__ __forceinline__ float2 unpack2(u64 v) {
    float2 f;
    asm("mov.b64 {%0, %1}, %2;" : "=f"(f.x), "=f"(f.y) : "l"(v));
    return f;
}

// Dual-edge half-width GEMM step: 24 outputs (12 u64 accs) per edge,
// sharing every weight broadcast between the two edges.
// ws points at (W + half*24), row stride D floats. bs at (b + half*24).
__device__ __forceinline__ void gemm48_half_dual(const float x0[D], const float x1[D],
                                                 u64 a0[12], u64 a1[12],
                                                 const float* __restrict__ ws,
                                                 const float* __restrict__ bs) {
#pragma unroll
    for (int j = 0; j < 12; j++) {
        u64 b = *(const u64*)(bs + 2 * j);
        a0[j] = b;
        a1[j] = b;
    }
#pragma unroll 4
    for (int k = 0; k < D; k++) {
        u64 xk0 = pack2(x0[k], x0[k]);
        u64 xk1 = pack2(x1[k], x1[k]);
        const ulonglong2* wr = (const ulonglong2*)(ws + k * D);
#pragma unroll
        for (int jj = 0; jj < 6; jj++) {
            ulonglong2 w = wr[jj];
            a0[2 * jj]     = fma2(xk0, w.x, a0[2 * jj]);
            a0[2 * jj + 1] = fma2(xk0, w.y, a0[2 * jj + 1]);
            a1[2 * jj]     = fma2(xk1, w.x, a1[2 * jj]);
            a1[2 * jj + 1] = fma2(xk1, w.y, a1[2 * jj + 1]);
        }
    }
}

// Dual-edge MLP: out{0,1} = relu(x{0,1}@W1 + b1) @ W2 + b2
__device__ __forceinline__ void mlp2_48_dual(const float x0[D], const float x1[D],
                                             float out0[D], float out1[D],
                                             const float* __restrict__ w1s, const float* __restrict__ b1s,
                                             const float* __restrict__ w2s, const float* __restrict__ b2s) {
    float h0[D], h1[D];
#pragma unroll 1
    for (int half = 0; half < 2; half++) {
        u64 a0[12], a1[12];
        gemm48_half_dual(x0, x1, a0, a1, w1s + half * 24, b1s + half * 24);
#pragma unroll
        for (int j = 0; j < 12; j++) {
            float2 v0 = unpack2(a0[j]);
            float2 v1 = unpack2(a1[j]);
            h0[half * 24 + 2 * j]     = fmaxf(v0.x, 0.f);
            h0[half * 24 + 2 * j + 1] = fmaxf(v0.y, 0.f);
            h1[half * 24 + 2 * j]     = fmaxf(v1.x, 0.f);
            h1[half * 24 + 2 * j + 1] = fmaxf(v1.y, 0.f);
        }
    }
#pragma unroll 1
    for (int half = 0; half < 2; half++) {
        u64 a0[12], a1[12];
        gemm48_half_dual(h0, h1, a0, a1, w2s + half * 24, b2s + half * 24);
#pragma unroll
        for (int j = 0; j < 12; j++) {
            float2 v0 = unpack2(a0[j]);
            float2 v1 = unpack2(a1[j]);
            out0[half * 24 + 2 * j]     = v0.x;
            out0[half * 24 + 2 * j + 1] = v0.y;
            out1[half * 24 + 2 * j]     = v1.x;
            out1[half * 24 + 2 * j + 1] = v1.y;
        }
    }
}

// Single-row half GEMM (for node update / readout kernels).
__device__ __forceinline__ void gemm48_half(const float x[D], u64 acc[12],
                                            const float* __restrict__ ws,
                                            const float* __restrict__ bs) {
#pragma unroll
    for (int j = 0; j < 12; j++) acc[j] = *(const u64*)(bs + 2 * j);
#pragma unroll 4
    for (int k = 0; k < D; k++) {
        u64 xk = pack2(x[k], x[k]);
        const ulonglong2* wr = (const ulonglong2*)(ws + k * D);
#pragma unroll
        for (int jj = 0; jj < 6; jj++) {
            ulonglong2 w = wr[jj];
            acc[2 * jj]     = fma2(xk, w.x, acc[2 * jj]);
            acc[2 * jj + 1] = fma2(xk, w.y, acc[2 * jj + 1]);
        }
    }
}

__device__ __forceinline__ void mlp2_48(const float x[D], float out[D],
                                        const float* __restrict__ w1s, const float* __restrict__ b1s,
                                        const float* __restrict__ w2s, const float* __restrict__ b2s) {
    float hid[D];
#pragma unroll 1
    for (int half = 0; half < 2; half++) {
        u64 acc[12];
        gemm48_half(x, acc, w1s + half * 24, b1s + half * 24);
#pragma unroll
        for (int j = 0; j < 12; j++) {
            float2 v = unpack2(acc[j]);
            hid[half * 24 + 2 * j]     = fmaxf(v.x, 0.f);
            hid[half * 24 + 2 * j + 1] = fmaxf(v.y, 0.f);
        }
    }
#pragma unroll 1
    for (int half = 0; half < 2; half++) {
        u64 acc[12];
        gemm48_half(hid, acc, w2s + half * 24, b2s + half * 24);
#pragma unroll
        for (int j = 0; j < 12; j++) {
            float2 v = unpack2(acc[j]);
            out[half * 24 + 2 * j]     = v.x;
            out[half * 24 + 2 * j + 1] = v.y;
        }
    }
}

// ---------- kernels ----------

__global__ void embed_kernel(const int* __restrict__ an, const float4* __restrict__ emb4) {
    int i = blockIdx.x * blockDim.x + threadIdx.x;  // over NN*12
    if (i >= NN * 12) return;
    int node = i / 12;
    int v = i - node * 12;
    g_h[i] = emb4[an[node] * 12 + v];
    g_agg[i] = make_float4(0.f, 0.f, 0.f, 0.f);
}

// shared layout: [0:2304) w1, [2304:4608) w2, [4608:4656) b1, [4656:4704) b2
__device__ __forceinline__ void load_weights_smem(float* s,
                                                  const float* __restrict__ w1, const float* __restrict__ b1,
                                                  const float* __restrict__ w2, const float* __restrict__ b2,
                                                  int layer) {
    const float* lw1 = w1 + layer * D * D;
    const float* lw2 = w2 + layer * D * D;
    for (int i = threadIdx.x; i < D * D; i += blockDim.x) {
        s[i] = lw1[i];
        s[2304 + i] = lw2[i];
    }
    if (threadIdx.x < D) {
        s[4608 + threadIdx.x] = b1[layer * D + threadIdx.x];
        s[4656 + threadIdx.x] = b2[layer * D + threadIdx.x];
    }
    __syncthreads();
}

__device__ __forceinline__ void gather_x(int srcn, int dstn, float x[D]) {
    const float4* hs = &g_h[srcn * 12];
    const float4* hd = &g_h[dstn * 12];
#pragma unroll
    for (int v = 0; v < 12; v++) {
        float4 a = hs[v];
        float4 b = hd[v];
        x[4 * v + 0] = a.x * b.x;
        x[4 * v + 1] = a.y * b.y;
        x[4 * v + 2] = a.z * b.z;
        x[4 * v + 3] = a.w * b.w;
    }
}

__device__ __forceinline__ void scatter_m(int dstn, const float m[D]) {
    float* aggp = (float*)&g_agg[dstn * 12];
#pragma unroll
    for (int v = 0; v < 12; v++) {
        asm volatile("red.global.add.v4.f32 [%0], {%1, %2, %3, %4};"
                     :: "l"(aggp + 4 * v),
                        "f"(m[4 * v]), "f"(m[4 * v + 1]), "f"(m[4 * v + 2]), "f"(m[4 * v + 3])
                     : "memory");
    }
}

// Each thread handles TWO edges, sharing every weight broadcast between them.
__global__ __launch_bounds__(256, 1) void edge_kernel(
    const int* __restrict__ edge,
    const float* __restrict__ w1, const float* __restrict__ b1,
    const float* __restrict__ w2, const float* __restrict__ b2, int layer) {
    __shared__ __align__(16) float s[4704];
    load_weights_smem(s, w1, b1, w2, b2, layer);

    int e0 = blockIdx.x * 512 + threadIdx.x;  // NE divisible by 512
    int e1 = e0 + 256;

    int src0 = edge[e0];
    int dst0 = edge[NE + e0];
    int src1 = edge[e1];
    int dst1 = edge[NE + e1];

    float x0[D], x1[D];
    gather_x(src0, dst0, x0);
    gather_x(src1, dst1, x1);

    float m0[D], m1[D];
    mlp2_48_dual(x0, x1, m0, m1, s, s + 4608, s + 2304, s + 4656);

    scatter_m(dst0, m0);
    scatter_m(dst1, m1);
}

__global__ __launch_bounds__(256, 2) void update_kernel(
    const float* __restrict__ w1, const float* __restrict__ b1,
    const float* __restrict__ w2, const float* __restrict__ b2, int layer) {
    __shared__ __align__(16) float s[4704];
    load_weights_smem(s, w1, b1, w2, b2, layer);

    int n = blockIdx.x * 256 + threadIdx.x;
    if (n >= NN) return;

    float4* aggp = &g_agg[n * 12];
    float x[D];
    const float4 z = make_float4(0.f, 0.f, 0.f, 0.f);
#pragma unroll
    for (int v = 0; v < 12; v++) {
        float4 a = aggp[v];
        x[4 * v + 0] = a.x;
        x[4 * v + 1] = a.y;
        x[4 * v + 2] = a.z;
        x[4 * v + 3] = a.w;
        aggp[v] = z;  // reset for next layer's scatter
    }

    float u[D];
    mlp2_48(x, u, s, s + 4608, s + 2304, s + 4656);

    float4* hp = &g_h[n * 12];
#pragma unroll
    for (int v = 0; v < 12; v++) {
        float4 h = hp[v];
        h.x += u[4 * v + 0];
        h.y += u[4 * v + 1];
        h.z += u[4 * v + 2];
        h.w += u[4 * v + 3];
        hp[v] = h;
    }
}

__global__ __launch_bounds__(256, 2) void readout_kernel(
    const int* __restrict__ gid,
    const float* __restrict__ rw1, const float* __restrict__ rb1,
    const float* __restrict__ rw2, const float* __restrict__ rb2,
    float* __restrict__ out) {
    // shared: [0:2304) w1, [2304:2352) b1, [2352:2400) w2 (48x1), [2400] b2
    __shared__ __align__(16) float s[2402];
    for (int i = threadIdx.x; i < D * D; i += blockDim.x) s[i] = rw1[i];
    if (threadIdx.x < D) {
        s[2304 + threadIdx.x] = rb1[threadIdx.x];
        s[2352 + threadIdx.x] = rw2[threadIdx.x];
    }
    if (threadIdx.x == 0) s[2400] = rb2[0];
    __syncthreads();

    int n = blockIdx.x * 256 + threadIdx.x;
    if (n >= NN) return;

    const float4* hp = &g_h[n * 12];
    float x[D];
#pragma unroll
    for (int v = 0; v < 12; v++) {
        float4 a = hp[v];
        x[4 * v + 0] = a.x;
        x[4 * v + 1] = a.y;
        x[4 * v + 2] = a.z;
        x[4 * v + 3] = a.w;
    }

    float y = s[2400];
#pragma unroll 1
    for (int half = 0; half < 2; half++) {
        u64 acc[12];
        gemm48_half(x, acc, s + half * 24, s + 2304 + half * 24);
#pragma unroll
        for (int j = 0; j < 12; j++) {
            float2 v = unpack2(acc[j]);
            y += fmaxf(v.x, 0.f) * s[2352 + half * 24 + 2 * j];
            y += fmaxf(v.y, 0.f) * s[2352 + half * 24 + 2 * j + 1];
        }
    }

    atomicAdd(&out[gid[n]], y);
}

extern "C" void kernel_launch(void* const* d_in, const int* in_sizes, int n_in,
                              void* d_out, int out_size) {
    const int*   an   = (const int*)d_in[0];
    const int*   edge = (const int*)d_in[1];
    const int*   gid  = (const int*)d_in[2];
    const float* emb  = (const float*)d_in[3];
    const float* mw1  = (const float*)d_in[4];
    const float* mb1  = (const float*)d_in[5];
    const float* mw2  = (const float*)d_in[6];
    const float* mb2  = (const float*)d_in[7];
    const float* uw1  = (const float*)d_in[8];
    const float* ub1  = (const float*)d_in[9];
    const float* uw2  = (const float*)d_in[10];
    const float* ub2  = (const float*)d_in[11];
    const float* rw1  = (const float*)d_in[12];
    const float* rb1  = (const float*)d_in[13];
    const float* rw2  = (const float*)d_in[14];
    const float* rb2  = (const float*)d_in[15];
    float* out = (float*)d_out;

    embed_kernel<<<(NN * 12 + 255) / 256, 256>>>(an, (const float4*)emb);

    for (int l = 0; l < NCONVS; l++) {
        edge_kernel<<<NE / 512, 256>>>(edge, mw1, mb1, mw2, mb2, l);
        update_kernel<<<(NN + 255) / 256, 256>>>(uw1, ub1, uw2, ub2, l);
    }

    cudaMemsetAsync(out, 0, NG * sizeof(float));
    readout_kernel<<<(NN + 255) / 256, 256>>>(gid, rw1, rb1, rw2, rb2, out);
}

// round 7
// speedup vs baseline: 1.6121x; 1.4143x over previous
#include <cuda_runtime.h>

#define NN 100000
#define NE 1600000
#define D 48
#define NCONVS 6
#define NG 1000

#define EPC 256     // edges per CTA (128 threads, 2 edges/thread)
#define XSTRIDE 49  // padded x row stride in floats (odd -> conflict-free scalar LDS)

typedef unsigned long long u64;

// Scratch state (no allocation allowed): node features + aggregation buffer.
__device__ float4 g_h[NN * 12];
__device__ float4 g_agg[NN * 12];

// ---------- packed f32x2 helpers ----------
__device__ __forceinline__ u64 fma2(u64 a, u64 b, u64 c) {
    u64 d;
    asm("fma.rn.f32x2 %0, %1, %2, %3;" : "=l"(d) : "l"(a), "l"(b), "l"(c));
    return d;
}
__device__ __forceinline__ u64 pack2(float lo, float hi) {
    u64 r;
    asm("mov.b64 %0, {%1, %2};" : "=l"(r) : "f"(lo), "f"(hi));
    return r;
}
__device__ __forceinline__ float2 unpack2(u64 v) {
    float2 f;
    asm("mov.b64 {%0, %1}, %2;" : "=f"(f.x), "=f"(f.y) : "l"(v));
    return f;
}

// ---------- dual-edge full-width GEMM reading x from SMEM ----------
// acc{0,1}[24] = bias ; acc += x{0,1} @ W   (W row-major [48][48] in smem)
// x0,x1 are per-thread rows in SMEM (stride-49, conflict-free scalar reads).
__device__ __forceinline__ void gemm48_dual_smem(const float* __restrict__ x0,
                                                 const float* __restrict__ x1,
                                                 u64 acc0[24], u64 acc1[24],
                                                 const float* __restrict__ ws,
                                                 const float* __restrict__ bs) {
#pragma unroll
    for (int j = 0; j < 24; j++) {
        u64 b = *(const u64*)(bs + 2 * j);
        acc0[j] = b;
        acc1[j] = b;
    }
#pragma unroll 4
    for (int k = 0; k < D; k++) {
        float a0 = x0[k];
        float a1 = x1[k];
        u64 xk0 = pack2(a0, a0);
        u64 xk1 = pack2(a1, a1);
        const ulonglong2* wr = (const ulonglong2*)(ws + k * D);
#pragma unroll
        for (int jj = 0; jj < 12; jj++) {
            ulonglong2 w = wr[jj];
            acc0[2 * jj]     = fma2(xk0, w.x, acc0[2 * jj]);
            acc0[2 * jj + 1] = fma2(xk0, w.y, acc0[2 * jj + 1]);
            acc1[2 * jj]     = fma2(xk1, w.x, acc1[2 * jj]);
            acc1[2 * jj + 1] = fma2(xk1, w.y, acc1[2 * jj + 1]);
        }
    }
}

// ---------- single-row half GEMM (update / readout kernels) ----------
__device__ __forceinline__ void gemm48_half(const float x[D], u64 acc[12],
                                            const float* __restrict__ ws,
                                            const float* __restrict__ bs) {
#pragma unroll
    for (int j = 0; j < 12; j++) acc[j] = *(const u64*)(bs + 2 * j);
#pragma unroll 4
    for (int k = 0; k < D; k++) {
        u64 xk = pack2(x[k], x[k]);
        const ulonglong2* wr = (const ulonglong2*)(ws + k * D);
#pragma unroll
        for (int jj = 0; jj < 6; jj++) {
            ulonglong2 w = wr[jj];
            acc[2 * jj]     = fma2(xk, w.x, acc[2 * jj]);
            acc[2 * jj + 1] = fma2(xk, w.y, acc[2 * jj + 1]);
        }
    }
}

__device__ __forceinline__ void mlp2_48(const float x[D], float out[D],
                                        const float* __restrict__ w1s, const float* __restrict__ b1s,
                                        const float* __restrict__ w2s, const float* __restrict__ b2s) {
    float hid[D];
#pragma unroll 1
    for (int half = 0; half < 2; half++) {
        u64 acc[12];
        gemm48_half(x, acc, w1s + half * 24, b1s + half * 24);
#pragma unroll
        for (int j = 0; j < 12; j++) {
            float2 v = unpack2(acc[j]);
            hid[half * 24 + 2 * j]     = fmaxf(v.x, 0.f);
            hid[half * 24 + 2 * j + 1] = fmaxf(v.y, 0.f);
        }
    }
#pragma unroll 1
    for (int half = 0; half < 2; half++) {
        u64 acc[12];
        gemm48_half(hid, acc, w2s + half * 24, b2s + half * 24);
#pragma unroll
        for (int j = 0; j < 12; j++) {
            float2 v = unpack2(acc[j]);
            out[half * 24 + 2 * j]     = v.x;
            out[half * 24 + 2 * j + 1] = v.y;
        }
    }
}

// ---------- kernels ----------

__global__ void embed_kernel(const int* __restrict__ an, const float4* __restrict__ emb4) {
    int i = blockIdx.x * blockDim.x + threadIdx.x;
    if (i >= NN * 12) return;
    int node = i / 12;
    int v = i - node * 12;
    g_h[i] = emb4[an[node] * 12 + v];
    g_agg[i] = make_float4(0.f, 0.f, 0.f, 0.f);
}

// Edge kernel:
//  SMEM layout (dynamic): [0:2304) w1, [2304:4608) w2, [4608:4656) b1,
//  [4656:4704) b2, [4704:4704+256*49) x rows (stride 49 floats).
//  Phase 1: cooperative coalesced gather — 4 lanes per edge stage
//           x[e] = h[src]*h[dst] into SMEM.
//  Phase 2: each thread runs the 2-layer MLP for 2 edges (e=tid, tid+128),
//           weights broadcast-shared, x re-read from SMEM (conflict-free).
#define EDGE_SMEM_FLOATS (4704 + EPC * XSTRIDE)

__global__ __launch_bounds__(128, 3) void edge_kernel(
    const int* __restrict__ edge,
    const float* __restrict__ w1, const float* __restrict__ b1,
    const float* __restrict__ w2, const float* __restrict__ b2, int layer) {
    extern __shared__ __align__(16) float s[];
    float* xs = s + 4704;
    int tid = threadIdx.x;

    // weights -> smem
    const float* lw1 = w1 + layer * D * D;
    const float* lw2 = w2 + layer * D * D;
#pragma unroll
    for (int i = tid; i < D * D; i += 128) {
        s[i] = lw1[i];
        s[2304 + i] = lw2[i];
    }
    if (tid < D) {
        s[4608 + tid] = b1[layer * D + tid];
        s[4656 + tid] = b2[layer * D + tid];
    }

    // Phase 1: staged gather. 256 edges * 4 chunks (12 floats each) = 1024 tasks.
    int e_base = blockIdx.x * EPC;
#pragma unroll
    for (int it = 0; it < 8; it++) {
        int idx = it * 128 + tid;      // 0..1023
        int el = idx >> 2;             // local edge 0..255
        int ch = idx & 3;              // chunk 0..3
        int e = e_base + el;
        int sn = edge[e];
        int dn = edge[NE + e];
        const float4* hs = (const float4*)&g_h[sn * 12] + ch * 3;
        const float4* hd = (const float4*)&g_h[dn * 12] + ch * 3;
        float* xrow = xs + el * XSTRIDE + ch * 12;
#pragma unroll
        for (int i = 0; i < 3; i++) {
            float4 a = hs[i];
            float4 b = hd[i];
            xrow[4 * i + 0] = a.x * b.x;
            xrow[4 * i + 1] = a.y * b.y;
            xrow[4 * i + 2] = a.z * b.z;
            xrow[4 * i + 3] = a.w * b.w;
        }
    }
    __syncthreads();

    // Phase 2: dual-edge MLP. e0 = tid, e1 = tid+128 (local).
    float* x0 = xs + tid * XSTRIDE;
    float* x1 = xs + (tid + 128) * XSTRIDE;

    {
        u64 a0[24], a1[24];
        gemm48_dual_smem(x0, x1, a0, a1, s, s + 4608);
        // relu -> write hidden back into own x rows (same-thread, no sync needed)
#pragma unroll
        for (int j = 0; j < 24; j++) {
            float2 v0 = unpack2(a0[j]);
            float2 v1 = unpack2(a1[j]);
            x0[2 * j]     = fmaxf(v0.x, 0.f);
            x0[2 * j + 1] = fmaxf(v0.y, 0.f);
            x1[2 * j]     = fmaxf(v1.x, 0.f);
            x1[2 * j + 1] = fmaxf(v1.y, 0.f);
        }
    }

    u64 a0[24], a1[24];
    gemm48_dual_smem(x0, x1, a0, a1, s + 2304, s + 4656);

    int dst0 = edge[NE + e_base + tid];
    int dst1 = edge[NE + e_base + tid + 128];
    float* agg0 = (float*)&g_agg[dst0 * 12];
    float* agg1 = (float*)&g_agg[dst1 * 12];
#pragma unroll
    for (int v = 0; v < 6; v++) {
        float2 p0 = unpack2(a0[4 * v + 0]);
        float2 p1 = unpack2(a0[4 * v + 1]);
        float2 p2 = unpack2(a0[4 * v + 2]);
        float2 p3 = unpack2(a0[4 * v + 3]);
        asm volatile("red.global.add.v4.f32 [%0], {%1, %2, %3, %4};"
                     :: "l"(agg0 + 8 * v), "f"(p0.x), "f"(p0.y), "f"(p1.x), "f"(p1.y) : "memory");
        asm volatile("red.global.add.v4.f32 [%0], {%1, %2, %3, %4};"
                     :: "l"(agg0 + 8 * v + 4), "f"(p2.x), "f"(p2.y), "f"(p3.x), "f"(p3.y) : "memory");
        float2 q0 = unpack2(a1[4 * v + 0]);
        float2 q1 = unpack2(a1[4 * v + 1]);
        float2 q2 = unpack2(a1[4 * v + 2]);
        float2 q3 = unpack2(a1[4 * v + 3]);
        asm volatile("red.global.add.v4.f32 [%0], {%1, %2, %3, %4};"
                     :: "l"(agg1 + 8 * v), "f"(q0.x), "f"(q0.y), "f"(q1.x), "f"(q1.y) : "memory");
        asm volatile("red.global.add.v4.f32 [%0], {%1, %2, %3, %4};"
                     :: "l"(agg1 + 8 * v + 4), "f"(q2.x), "f"(q2.y), "f"(q3.x), "f"(q3.y) : "memory");
    }
}

__device__ __forceinline__ void load_weights_smem(float* s,
                                                  const float* __restrict__ w1, const float* __restrict__ b1,
                                                  const float* __restrict__ w2, const float* __restrict__ b2,
                                                  int layer) {
    const float* lw1 = w1 + layer * D * D;
    const float* lw2 = w2 + layer * D * D;
    for (int i = threadIdx.x; i < D * D; i += blockDim.x) {
        s[i] = lw1[i];
        s[2304 + i] = lw2[i];
    }
    if (threadIdx.x < D) {
        s[4608 + threadIdx.x] = b1[layer * D + threadIdx.x];
        s[4656 + threadIdx.x] = b2[layer * D + threadIdx.x];
    }
    __syncthreads();
}

__global__ __launch_bounds__(256, 2) void update_kernel(
    const float* __restrict__ w1, const float* __restrict__ b1,
    const float* __restrict__ w2, const float* __restrict__ b2, int layer) {
    __shared__ __align__(16) float s[4704];
    load_weights_smem(s, w1, b1, w2, b2, layer);

    int n = blockIdx.x * 256 + threadIdx.x;
    if (n >= NN) return;

    float4* aggp = &g_agg[n * 12];
    float x[D];
    const float4 z = make_float4(0.f, 0.f, 0.f, 0.f);
#pragma unroll
    for (int v = 0; v < 12; v++) {
        float4 a = aggp[v];
        x[4 * v + 0] = a.x;
        x[4 * v + 1] = a.y;
        x[4 * v + 2] = a.z;
        x[4 * v + 3] = a.w;
        aggp[v] = z;  // reset for next layer's scatter
    }

    float u[D];
    mlp2_48(x, u, s, s + 4608, s + 2304, s + 4656);

    float4* hp = &g_h[n * 12];
#pragma unroll
    for (int v = 0; v < 12; v++) {
        float4 h = hp[v];
        h.x += u[4 * v + 0];
        h.y += u[4 * v + 1];
        h.z += u[4 * v + 2];
        h.w += u[4 * v + 3];
        hp[v] = h;
    }
}

__global__ __launch_bounds__(256, 2) void readout_kernel(
    const int* __restrict__ gid,
    const float* __restrict__ rw1, const float* __restrict__ rb1,
    const float* __restrict__ rw2, const float* __restrict__ rb2,
    float* __restrict__ out) {
    __shared__ __align__(16) float s[2402];
    for (int i = threadIdx.x; i < D * D; i += blockDim.x) s[i] = rw1[i];
    if (threadIdx.x < D) {
        s[2304 + threadIdx.x] = rb1[threadIdx.x];
        s[2352 + threadIdx.x] = rw2[threadIdx.x];
    }
    if (threadIdx.x == 0) s[2400] = rb2[0];
    __syncthreads();

    int n = blockIdx.x * 256 + threadIdx.x;
    if (n >= NN) return;

    const float4* hp = &g_h[n * 12];
    float x[D];
#pragma unroll
    for (int v = 0; v < 12; v++) {
        float4 a = hp[v];
        x[4 * v + 0] = a.x;
        x[4 * v + 1] = a.y;
        x[4 * v + 2] = a.z;
        x[4 * v + 3] = a.w;
    }

    float y = s[2400];
#pragma unroll 1
    for (int half = 0; half < 2; half++) {
        u64 acc[12];
        gemm48_half(x, acc, s + half * 24, s + 2304 + half * 24);
#pragma unroll
        for (int j = 0; j < 12; j++) {
            float2 v = unpack2(acc[j]);
            y += fmaxf(v.x, 0.f) * s[2352 + half * 24 + 2 * j];
            y += fmaxf(v.y, 0.f) * s[2352 + half * 24 + 2 * j + 1];
        }
    }

    atomicAdd(&out[gid[n]], y);
}

extern "C" void kernel_launch(void* const* d_in, const int* in_sizes, int n_in,
                              void* d_out, int out_size) {
    const int*   an   = (const int*)d_in[0];
    const int*   edge = (const int*)d_in[1];
    const int*   gid  = (const int*)d_in[2];
    const float* emb  = (const float*)d_in[3];
    const float* mw1  = (const float*)d_in[4];
    const float* mb1  = (const float*)d_in[5];
    const float* mw2  = (const float*)d_in[6];
    const float* mb2  = (const float*)d_in[7];
    const float* uw1  = (const float*)d_in[8];
    const float* ub1  = (const float*)d_in[9];
    const float* uw2  = (const float*)d_in[10];
    const float* ub2  = (const float*)d_in[11];
    const float* rw1  = (const float*)d_in[12];
    const float* rb1  = (const float*)d_in[13];
    const float* rw2  = (const float*)d_in[14];
    const float* rb2  = (const float*)d_in[15];
    float* out = (float*)d_out;

    const int edge_smem = EDGE_SMEM_FLOATS * (int)sizeof(float);  // ~69 KB
    cudaFuncSetAttribute(edge_kernel, cudaFuncAttributeMaxDynamicSharedMemorySize, edge_smem);

    embed_kernel<<<(NN * 12 + 255) / 256, 256>>>(an, (const float4*)emb);

    for (int l = 0; l < NCONVS; l++) {
        edge_kernel<<<NE / EPC, 128, edge_smem>>>(edge, mw1, mb1, mw2, mb2, l);
        update_kernel<<<(NN + 255) / 256, 256>>>(uw1, ub1, uw2, ub2, l);
    }

    cudaMemsetAsync(out, 0, NG * sizeof(float));
    readout_kernel<<<(NN + 255) / 256, 256>>>(gid, rw1, rb1, rw2, rb2, out);
}

// round 8
// speedup vs baseline: 1.7006x; 1.0549x over previous
#include <cuda_runtime.h>

#define NN 100000
#define NE 1600000
#define D 48
#define NCONVS 6
#define NG 1000

#define EPC 256     // edges per CTA (128 threads, 2 consecutive edges/thread)
#define XSTRIDE 49  // padded x row stride in floats (odd -> conflict-free scalar LDS)

#define SCAN_BLK 1024
#define NSCAN_BLKS ((NN + SCAN_BLK - 1) / SCAN_BLK)   // 98

typedef unsigned long long u64;

// Scratch state (no allocation allowed).
__device__ float4 g_h[NN * 12];
__device__ float4 g_agg[NN * 12];
// counting-sort scratch
__device__ int g_cnt[NN];
__device__ int g_scan[NN];
__device__ int g_bsum[NSCAN_BLKS];
__device__ int g_woff[NN];
__device__ int g_ssrc[NE];
__device__ int g_sdst[NE];

// ---------- packed f32x2 helpers ----------
__device__ __forceinline__ u64 fma2(u64 a, u64 b, u64 c) {
    u64 d;
    asm("fma.rn.f32x2 %0, %1, %2, %3;" : "=l"(d) : "l"(a), "l"(b), "l"(c));
    return d;
}
__device__ __forceinline__ u64 add2(u64 a, u64 b) {
    u64 d;
    asm("add.rn.f32x2 %0, %1, %2;" : "=l"(d) : "l"(a), "l"(b));
    return d;
}
__device__ __forceinline__ u64 pack2(float lo, float hi) {
    u64 r;
    asm("mov.b64 %0, {%1, %2};" : "=l"(r) : "f"(lo), "f"(hi));
    return r;
}
__device__ __forceinline__ float2 unpack2(u64 v) {
    float2 f;
    asm("mov.b64 {%0, %1}, %2;" : "=f"(f.x), "=f"(f.y) : "l"(v));
    return f;
}

// ---------- counting sort by dst ----------
__global__ void zero_cnt_kernel() {
    int i = blockIdx.x * blockDim.x + threadIdx.x;
    if (i < NN) g_cnt[i] = 0;
}
__global__ void hist_kernel(const int* __restrict__ edge) {
    int e = blockIdx.x * blockDim.x + threadIdx.x;
    if (e < NE) atomicAdd(&g_cnt[edge[NE + e]], 1);
}
__global__ void scan1_kernel() {
    __shared__ int sh[SCAN_BLK];
    int tid = threadIdx.x;
    int i = blockIdx.x * SCAN_BLK + tid;
    int v = (i < NN) ? g_cnt[i] : 0;
    sh[tid] = v;
    __syncthreads();
#pragma unroll
    for (int o = 1; o < SCAN_BLK; o <<= 1) {
        int t = (tid >= o) ? sh[tid - o] : 0;
        __syncthreads();
        sh[tid] += t;
        __syncthreads();
    }
    if (i < NN) g_scan[i] = sh[tid];
    if (tid == SCAN_BLK - 1) g_bsum[blockIdx.x] = sh[tid];
}
__global__ void scan2_kernel() {
    if (threadIdx.x == 0 && blockIdx.x == 0) {
        int acc = 0;
        for (int b = 0; b < NSCAN_BLKS; b++) {
            int t = g_bsum[b];
            g_bsum[b] = acc;
            acc += t;
        }
    }
}
__global__ void scan3_kernel() {
    int i = blockIdx.x * blockDim.x + threadIdx.x;
    if (i < NN) g_woff[i] = g_scan[i] - g_cnt[i] + g_bsum[i / SCAN_BLK];
}
__global__ void scatter_sort_kernel(const int* __restrict__ edge) {
    int e = blockIdx.x * blockDim.x + threadIdx.x;
    if (e >= NE) return;
    int d = edge[NE + e];
    int pos = atomicAdd(&g_woff[d], 1);
    g_ssrc[pos] = edge[e];
    g_sdst[pos] = d;
}

// ---------- dual-edge full-width GEMM reading x from SMEM ----------
__device__ __forceinline__ void gemm48_dual_smem(const float* __restrict__ x0,
                                                 const float* __restrict__ x1,
                                                 u64 acc0[24], u64 acc1[24],
                                                 const float* __restrict__ ws,
                                                 const float* __restrict__ bs) {
#pragma unroll
    for (int j = 0; j < 24; j++) {
        u64 b = *(const u64*)(bs + 2 * j);
        acc0[j] = b;
        acc1[j] = b;
    }
#pragma unroll 4
    for (int k = 0; k < D; k++) {
        float a0 = x0[k];
        float a1 = x1[k];
        u64 xk0 = pack2(a0, a0);
        u64 xk1 = pack2(a1, a1);
        const ulonglong2* wr = (const ulonglong2*)(ws + k * D);
#pragma unroll
        for (int jj = 0; jj < 12; jj++) {
            ulonglong2 w = wr[jj];
            acc0[2 * jj]     = fma2(xk0, w.x, acc0[2 * jj]);
            acc0[2 * jj + 1] = fma2(xk0, w.y, acc0[2 * jj + 1]);
            acc1[2 * jj]     = fma2(xk1, w.x, acc1[2 * jj]);
            acc1[2 * jj + 1] = fma2(xk1, w.y, acc1[2 * jj + 1]);
        }
    }
}

// ---------- single-row half GEMM (update / readout) ----------
__device__ __forceinline__ void gemm48_half(const float x[D], u64 acc[12],
                                            const float* __restrict__ ws,
                                            const float* __restrict__ bs) {
#pragma unroll
    for (int j = 0; j < 12; j++) acc[j] = *(const u64*)(bs + 2 * j);
#pragma unroll 4
    for (int k = 0; k < D; k++) {
        u64 xk = pack2(x[k], x[k]);
        const ulonglong2* wr = (const ulonglong2*)(ws + k * D);
#pragma unroll
        for (int jj = 0; jj < 6; jj++) {
            ulonglong2 w = wr[jj];
            acc[2 * jj]     = fma2(xk, w.x, acc[2 * jj]);
            acc[2 * jj + 1] = fma2(xk, w.y, acc[2 * jj + 1]);
        }
    }
}

__device__ __forceinline__ void mlp2_48(const float x[D], float out[D],
                                        const float* __restrict__ w1s, const float* __restrict__ b1s,
                                        const float* __restrict__ w2s, const float* __restrict__ b2s) {
    float hid[D];
#pragma unroll 1
    for (int half = 0; half < 2; half++) {
        u64 acc[12];
        gemm48_half(x, acc, w1s + half * 24, b1s + half * 24);
#pragma unroll
        for (int j = 0; j < 12; j++) {
            float2 v = unpack2(acc[j]);
            hid[half * 24 + 2 * j]     = fmaxf(v.x, 0.f);
            hid[half * 24 + 2 * j + 1] = fmaxf(v.y, 0.f);
        }
    }
#pragma unroll 1
    for (int half = 0; half < 2; half++) {
        u64 acc[12];
        gemm48_half(hid, acc, w2s + half * 24, b2s + half * 24);
#pragma unroll
        for (int j = 0; j < 12; j++) {
            float2 v = unpack2(acc[j]);
            out[half * 24 + 2 * j]     = v.x;
            out[half * 24 + 2 * j + 1] = v.y;
        }
    }
}

// ---------- kernels ----------

__global__ void embed_kernel(const int* __restrict__ an, const float4* __restrict__ emb4) {
    int i = blockIdx.x * blockDim.x + threadIdx.x;
    if (i >= NN * 12) return;
    int node = i / 12;
    int v = i - node * 12;
    g_h[i] = emb4[an[node] * 12 + v];
    g_agg[i] = make_float4(0.f, 0.f, 0.f, 0.f);
}

__device__ __forceinline__ void scatter48(float* aggp, const u64 a[24]) {
#pragma unroll
    for (int v = 0; v < 6; v++) {
        float2 p0 = unpack2(a[4 * v + 0]);
        float2 p1 = unpack2(a[4 * v + 1]);
        float2 p2 = unpack2(a[4 * v + 2]);
        float2 p3 = unpack2(a[4 * v + 3]);
        asm volatile("red.global.add.v4.f32 [%0], {%1, %2, %3, %4};"
                     :: "l"(aggp + 8 * v), "f"(p0.x), "f"(p0.y), "f"(p1.x), "f"(p1.y) : "memory");
        asm volatile("red.global.add.v4.f32 [%0], {%1, %2, %3, %4};"
                     :: "l"(aggp + 8 * v + 4), "f"(p2.x), "f"(p2.y), "f"(p3.x), "f"(p3.y) : "memory");
    }
}

// Edge kernel over dst-sorted edges.
//  SMEM: [0:2304) w1, [2304:4608) w2, [4608:4656) b1, [4656:4704) b2,
//        [4704: +256*49) x rows. Edge el -> row (el&1)*128 + (el>>1), so
//  phase-2 thread t reads rows t and t+128 = edges 2t, 2t+1 (consecutive,
//  usually same dst -> merged scatter), with conflict-free stride-49 LDS.
#define EDGE_SMEM_FLOATS (4704 + EPC * XSTRIDE)

__global__ __launch_bounds__(128, 3) void edge_kernel(
    const float* __restrict__ w1, const float* __restrict__ b1,
    const float* __restrict__ w2, const float* __restrict__ b2, int layer) {
    extern __shared__ __align__(16) float s[];
    float* xs = s + 4704;
    int tid = threadIdx.x;

    const float* lw1 = w1 + layer * D * D;
    const float* lw2 = w2 + layer * D * D;
#pragma unroll
    for (int i = tid; i < D * D; i += 128) {
        s[i] = lw1[i];
        s[2304 + i] = lw2[i];
    }
    if (tid < D) {
        s[4608 + tid] = b1[layer * D + tid];
        s[4656 + tid] = b2[layer * D + tid];
    }

    // Phase 1: coalesced gather, 4 lanes per edge.
    int e_base = blockIdx.x * EPC;
#pragma unroll
    for (int it = 0; it < 8; it++) {
        int idx = it * 128 + tid;      // 0..1023
        int el = idx >> 2;             // local edge 0..255
        int ch = idx & 3;              // chunk 0..3
        int e = e_base + el;
        int sn = g_ssrc[e];
        int dn = g_sdst[e];
        const float4* hs = (const float4*)&g_h[sn * 12] + ch * 3;
        const float4* hd = (const float4*)&g_h[dn * 12] + ch * 3;
        int row = ((el & 1) << 7) + (el >> 1);
        float* xrow = xs + row * XSTRIDE + ch * 12;
#pragma unroll
        for (int i = 0; i < 3; i++) {
            float4 a = hs[i];
            float4 b = hd[i];
            xrow[4 * i + 0] = a.x * b.x;
            xrow[4 * i + 1] = a.y * b.y;
            xrow[4 * i + 2] = a.z * b.z;
            xrow[4 * i + 3] = a.w * b.w;
        }
    }
    __syncthreads();

    // Phase 2: dual consecutive edges 2t, 2t+1.
    float* x0 = xs + tid * XSTRIDE;
    float* x1 = xs + (tid + 128) * XSTRIDE;

    {
        u64 a0[24], a1[24];
        gemm48_dual_smem(x0, x1, a0, a1, s, s + 4608);
#pragma unroll
        for (int j = 0; j < 24; j++) {
            float2 v0 = unpack2(a0[j]);
            float2 v1 = unpack2(a1[j]);
            x0[2 * j]     = fmaxf(v0.x, 0.f);
            x0[2 * j + 1] = fmaxf(v0.y, 0.f);
            x1[2 * j]     = fmaxf(v1.x, 0.f);
            x1[2 * j + 1] = fmaxf(v1.y, 0.f);
        }
    }

    u64 a0[24], a1[24];
    gemm48_dual_smem(x0, x1, a0, a1, s + 2304, s + 4656);

    int e0 = e_base + 2 * tid;
    int dst0 = g_sdst[e0];
    int dst1 = g_sdst[e0 + 1];
    if (dst0 == dst1) {
#pragma unroll
        for (int j = 0; j < 24; j++) a0[j] = add2(a0[j], a1[j]);
        scatter48((float*)&g_agg[dst0 * 12], a0);
    } else {
        scatter48((float*)&g_agg[dst0 * 12], a0);
        scatter48((float*)&g_agg[dst1 * 12], a1);
    }
}

__device__ __forceinline__ void load_weights_smem(float* s,
                                                  const float* __restrict__ w1, const float* __restrict__ b1,
                                                  const float* __restrict__ w2, const float* __restrict__ b2,
                                                  int layer) {
    const float* lw1 = w1 + layer * D * D;
    const float* lw2 = w2 + layer * D * D;
    for (int i = threadIdx.x; i < D * D; i += blockDim.x) {
        s[i] = lw1[i];
        s[2304 + i] = lw2[i];
    }
    if (threadIdx.x < D) {
        s[4608 + threadIdx.x] = b1[layer * D + threadIdx.x];
        s[4656 + threadIdx.x] = b2[layer * D + threadIdx.x];
    }
    __syncthreads();
}

__global__ __launch_bounds__(256, 2) void update_kernel(
    const float* __restrict__ w1, const float* __restrict__ b1,
    const float* __restrict__ w2, const float* __restrict__ b2, int layer) {
    __shared__ __align__(16) float s[4704];
    load_weights_smem(s, w1, b1, w2, b2, layer);

    int n = blockIdx.x * 256 + threadIdx.x;
    if (n >= NN) return;

    float4* aggp = &g_agg[n * 12];
    float x[D];
    const float4 z = make_float4(0.f, 0.f, 0.f, 0.f);
#pragma unroll
    for (int v = 0; v < 12; v++) {
        float4 a = aggp[v];
        x[4 * v + 0] = a.x;
        x[4 * v + 1] = a.y;
        x[4 * v + 2] = a.z;
        x[4 * v + 3] = a.w;
        aggp[v] = z;
    }

    float u[D];
    mlp2_48(x, u, s, s + 4608, s + 2304, s + 4656);

    float4* hp = &g_h[n * 12];
#pragma unroll
    for (int v = 0; v < 12; v++) {
        float4 h = hp[v];
        h.x += u[4 * v + 0];
        h.y += u[4 * v + 1];
        h.z += u[4 * v + 2];
        h.w += u[4 * v + 3];
        hp[v] = h;
    }
}

__global__ __launch_bounds__(256, 2) void readout_kernel(
    const int* __restrict__ gid,
    const float* __restrict__ rw1, const float* __restrict__ rb1,
    const float* __restrict__ rw2, const float* __restrict__ rb2,
    float* __restrict__ out) {
    __shared__ __align__(16) float s[2402];
    for (int i = threadIdx.x; i < D * D; i += blockDim.x) s[i] = rw1[i];
    if (threadIdx.x < D) {
        s[2304 + threadIdx.x] = rb1[threadIdx.x];
        s[2352 + threadIdx.x] = rw2[threadIdx.x];
    }
    if (threadIdx.x == 0) s[2400] = rb2[0];
    __syncthreads();

    int n = blockIdx.x * 256 + threadIdx.x;
    if (n >= NN) return;

    const float4* hp = &g_h[n * 12];
    float x[D];
#pragma unroll
    for (int v = 0; v < 12; v++) {
        float4 a = hp[v];
        x[4 * v + 0] = a.x;
        x[4 * v + 1] = a.y;
        x[4 * v + 2] = a.z;
        x[4 * v + 3] = a.w;
    }

    float y = s[2400];
#pragma unroll 1
    for (int half = 0; half < 2; half++) {
        u64 acc[12];
        gemm48_half(x, acc, s + half * 24, s + 2304 + half * 24);
#pragma unroll
        for (int j = 0; j < 12; j++) {
            float2 v = unpack2(acc[j]);
            y += fmaxf(v.x, 0.f) * s[2352 + half * 24 + 2 * j];
            y += fmaxf(v.y, 0.f) * s[2352 + half * 24 + 2 * j + 1];
        }
    }

    atomicAdd(&out[gid[n]], y);
}

extern "C" void kernel_launch(void* const* d_in, const int* in_sizes, int n_in,
                              void* d_out, int out_size) {
    const int*   an   = (const int*)d_in[0];
    const int*   edge = (const int*)d_in[1];
    const int*   gid  = (const int*)d_in[2];
    const float* emb  = (const float*)d_in[3];
    const float* mw1  = (const float*)d_in[4];
    const float* mb1  = (const float*)d_in[5];
    const float* mw2  = (const float*)d_in[6];
    const float* mb2  = (const float*)d_in[7];
    const float* uw1  = (const float*)d_in[8];
    const float* ub1  = (const float*)d_in[9];
    const float* uw2  = (const float*)d_in[10];
    const float* ub2  = (const float*)d_in[11];
    const float* rw1  = (const float*)d_in[12];
    const float* rb1  = (const float*)d_in[13];
    const float* rw2  = (const float*)d_in[14];
    const float* rb2  = (const float*)d_in[15];
    float* out = (float*)d_out;

    const int edge_smem = EDGE_SMEM_FLOATS * (int)sizeof(float);  // ~69 KB
    cudaFuncSetAttribute(edge_kernel, cudaFuncAttributeMaxDynamicSharedMemorySize, edge_smem);

    // counting sort of edges by dst (edge list constant across layers)
    zero_cnt_kernel<<<(NN + 255) / 256, 256>>>();
    hist_kernel<<<(NE + 255) / 256, 256>>>(edge);
    scan1_kernel<<<NSCAN_BLKS, SCAN_BLK>>>();
    scan2_kernel<<<1, 32>>>();
    scan3_kernel<<<(NN + 255) / 256, 256>>>();
    scatter_sort_kernel<<<(NE + 255) / 256, 256>>>(edge);

    embed_kernel<<<(NN * 12 + 255) / 256, 256>>>(an, (const float4*)emb);

    for (int l = 0; l < NCONVS; l++) {
        edge_kernel<<<NE / EPC, 128, edge_smem>>>(mw1, mb1, mw2, mb2, l);
        update_kernel<<<(NN + 255) / 256, 256>>>(uw1, ub1, uw2, ub2, l);
    }

    cudaMemsetAsync(out, 0, NG * sizeof(float));
    readout_kernel<<<(NN + 255) / 256, 256>>>(gid, rw1, rb1, rw2, rb2, out);
}